// round 12
// baseline (speedup 1.0000x reference)
#include <cuda_runtime.h>
#include <cuda_fp16.h>
#include <cstdint>

// Problem constants
#define BB   8
#define LL   1024
#define DIN  512
#define HH   8
#define DD   64
#define DOUT 512
#define MM   (BB * LL)   // 8192

// Half-precision staging buffers
__device__ __half g_xh[3 * MM * DIN];       // inputs converted to half
__device__ __half g_wth[3 * DIN * DOUT];    // Wt[n][k] half; WQ pre-scaled by 0.125*log2e
__device__ __half g_q [BB * HH * LL * DD];  // [b,h,l,d], pre-scaled
__device__ __half g_k [BB * HH * LL * DD];  // [b,h,l,d]
__device__ __half g_vt[BB * HH * DD * LL];  // [b,h,d,l]  (V transposed)

// ===========================================================================
// Helpers
// ===========================================================================
__device__ __forceinline__ float ex2f(float x) {
    float y;
    asm("ex2.approx.ftz.f32 %0, %1;" : "=f"(y) : "f"(x));
    return y;
}

__device__ __forceinline__ void mma_f16_16n8k16(float& d0, float& d1, float& d2, float& d3,
                                                uint32_t a0, uint32_t a1, uint32_t a2, uint32_t a3,
                                                uint32_t b0, uint32_t b1) {
    asm volatile(
        "mma.sync.aligned.m16n8k16.row.col.f32.f16.f16.f32 "
        "{%0,%1,%2,%3}, {%4,%5,%6,%7}, {%8,%9}, {%0,%1,%2,%3};"
        : "+f"(d0), "+f"(d1), "+f"(d2), "+f"(d3)
        : "r"(a0), "r"(a1), "r"(a2), "r"(a3), "r"(b0), "r"(b1));
}

__device__ __forceinline__ void ldmatrix_x4(uint32_t& r0, uint32_t& r1,
                                            uint32_t& r2, uint32_t& r3, uint32_t addr) {
    asm volatile("ldmatrix.sync.aligned.m8n8.x4.shared.b16 {%0,%1,%2,%3}, [%4];"
                 : "=r"(r0), "=r"(r1), "=r"(r2), "=r"(r3) : "r"(addr));
}

__device__ __forceinline__ uint32_t smem_u32(const void* p) {
    uint32_t a;
    asm("{ .reg .u64 t; cvta.to.shared.u64 t, %1; cvt.u32.u64 %0, t; }"
        : "=r"(a) : "l"(p));
    return a;
}

__device__ __forceinline__ uint32_t h2u(__half2 h) {
    uint32_t u;
    asm("mov.b32 %0, %1;" : "=r"(u) : "r"(*(uint32_t*)&h));
    return u;
}

#define CP_ASYNC16(dst_u32, src_ptr) \
    asm volatile("cp.async.cg.shared.global [%0], [%1], 16;" :: "r"(dst_u32), "l"(src_ptr))
#define CP_COMMIT()  asm volatile("cp.async.commit_group;" ::: "memory")
#define CP_WAIT0()   asm volatile("cp.async.wait_group 0;" ::: "memory")

// ===========================================================================
// Fused pre-pass: convert X->half (4 strided float4/thread) AND transpose W.
// grid = (1024 + 256, 1, 3), block = 256.
// ===========================================================================
__global__ void prepass_kernel(const float* __restrict__ Q, const float* __restrict__ K,
                               const float* __restrict__ V,
                               const float* __restrict__ Wq, const float* __restrict__ Wk,
                               const float* __restrict__ Wv)
{
    const int z  = blockIdx.z;
    const int bx = blockIdx.x;
    const int tid = threadIdx.x;

    if (bx < 1024) {
        const float* src = (z == 0) ? Q : (z == 1) ? K : V;
        __half2* dst = (__half2*)(g_xh + (size_t)z * MM * DIN);
        const int base = bx * 1024 + tid;
        float4 v[4];
        #pragma unroll
        for (int j = 0; j < 4; j++)
            v[j] = ((const float4*)src)[base + j * 256];
        #pragma unroll
        for (int j = 0; j < 4; j++) {
            const int i = base + j * 256;
            dst[2 * i + 0] = __floats2half2_rn(v[j].x, v[j].y);
            dst[2 * i + 1] = __floats2half2_rn(v[j].z, v[j].w);
        }
    } else {
        const float* W = (z == 0) ? Wq : (z == 1) ? Wk : Wv;
        __half* Wt = g_wth + (size_t)z * DIN * DOUT;
        const float s = (z == 0) ? 0.125f * 1.4426950408889634f : 1.0f;

        __shared__ float t[32][33];
        const int tile = bx - 1024;
        const int bxt  = tile & 15;
        const int byt  = tile >> 4;
        const int tx = tid & 31, ty = tid >> 5;
        int x = bxt * 32 + tx;
        int y = byt * 32 + ty;
        #pragma unroll
        for (int j = 0; j < 32; j += 8)
            t[ty + j][tx] = W[(size_t)(y + j) * DOUT + x];
        __syncthreads();
        x = byt * 32 + tx;
        y = bxt * 32 + ty;
        #pragma unroll
        for (int j = 0; j < 32; j += 8)
            Wt[(size_t)(y + j) * DIN + x] = __float2half(t[tx][ty + j] * s);
    }
}

// ===========================================================================
// fp16 mma.sync projection with ldmatrix fragment loads. (validated round 10)
// ===========================================================================
#define PTM 128
#define PTN 128
#define PTK 64
#define PKT (DIN / PTK)    // 8
#define PRH 72             // halves per smem row
#define PRW 36             // words per smem row
#define TILE_H (PTM * PRH)
#define SMEM_PROJ (4 * TILE_H * (int)sizeof(__half))   // 73728 B

__global__ __launch_bounds__(256)
void proj_mma_kernel()
{
    extern __shared__ __half smh[];
    __half* As[2] = { smh,              smh + TILE_H };
    __half* Bs[2] = { smh + 2 * TILE_H, smh + 3 * TILE_H };

    const int z = blockIdx.z;
    const __half* X  = g_xh  + (size_t)z * MM * DIN;
    const __half* Wt = g_wth + (size_t)z * DIN * DOUT;

    const int tid  = threadIdx.x;
    const int wid  = tid >> 5;
    const int lane = tid & 31;
    const int wm   = wid & 3;
    const int wn   = wid >> 2;
    const int m0   = blockIdx.y * PTM;
    const int n0   = blockIdx.x * PTN;
    const int lr   = lane >> 2;
    const int lc   = lane & 3;

    const int a_row = ((lane >> 3) & 1) * 8 + (lane & 7);
    const int a_kh  = (lane >> 4) * 8;
    const int b_row = (lane >> 4) * 8 + (lane & 7);
    const int b_kh  = ((lane >> 3) & 1) * 8;

    uint32_t dsto[4];
    const __half* a_src[4];
    const __half* b_src[4];
    #pragma unroll
    for (int i = 0; i < 4; i++) {
        const int idx = i * 256 + tid;
        const int r   = idx >> 3;
        const int c8  = idx & 7;
        dsto[i] = (uint32_t)((r * PRH + c8 * 8) * 2);
        a_src[i] = &X [(size_t)(m0 + r) * DIN + c8 * 8];
        b_src[i] = &Wt[(size_t)(n0 + r) * DIN + c8 * 8];
    }
    const uint32_t sa[2] = { smem_u32(As[0]), smem_u32(As[1]) };
    const uint32_t sb[2] = { smem_u32(Bs[0]), smem_u32(Bs[1]) };

    float acc[2][8][4];
    #pragma unroll
    for (int mt = 0; mt < 2; mt++)
        #pragma unroll
        for (int nt = 0; nt < 8; nt++)
            #pragma unroll
            for (int q = 0; q < 4; q++) acc[mt][nt][q] = 0.0f;

    #pragma unroll
    for (int i = 0; i < 4; i++) {
        CP_ASYNC16(sa[0] + dsto[i], a_src[i]);
        CP_ASYNC16(sb[0] + dsto[i], b_src[i]);
    }
    CP_COMMIT();
    CP_WAIT0();
    __syncthreads();

    for (int kt = 0; kt < PKT; kt++) {
        const int cur = kt & 1;
        if (kt + 1 < PKT) {
            const int nxt = cur ^ 1;
            const int koff = (kt + 1) * PTK;
            #pragma unroll
            for (int i = 0; i < 4; i++) {
                CP_ASYNC16(sa[nxt] + dsto[i], a_src[i] + koff);
                CP_ASYNC16(sb[nxt] + dsto[i], b_src[i] + koff);
            }
            CP_COMMIT();
        }

        const uint32_t Abase = sa[cur];
        const uint32_t Bbase = sb[cur];
        #pragma unroll
        for (int ks = 0; ks < 4; ks++) {
            uint32_t af[2][4];
            #pragma unroll
            for (int mt = 0; mt < 2; mt++) {
                const uint32_t addr = Abase +
                    (uint32_t)(((wm * 32 + mt * 16 + a_row) * PRH + ks * 16 + a_kh) * 2);
                ldmatrix_x4(af[mt][0], af[mt][1], af[mt][2], af[mt][3], addr);
            }
            uint32_t bf[8][2];
            #pragma unroll
            for (int ntp = 0; ntp < 4; ntp++) {
                const uint32_t addr = Bbase +
                    (uint32_t)(((wn * 64 + ntp * 16 + b_row) * PRH + ks * 16 + b_kh) * 2);
                ldmatrix_x4(bf[2 * ntp][0], bf[2 * ntp][1],
                            bf[2 * ntp + 1][0], bf[2 * ntp + 1][1], addr);
            }
            #pragma unroll
            for (int mt = 0; mt < 2; mt++)
                #pragma unroll
                for (int nt = 0; nt < 8; nt++)
                    mma_f16_16n8k16(acc[mt][nt][0], acc[mt][nt][1],
                                    acc[mt][nt][2], acc[mt][nt][3],
                                    af[mt][0], af[mt][1], af[mt][2], af[mt][3],
                                    bf[nt][0], bf[nt][1]);
        }

        if (kt + 1 < PKT) CP_WAIT0();
        __syncthreads();
    }

    if (z < 2) {
        __half* out = (z == 0) ? g_q : g_k;
        #pragma unroll
        for (int mt = 0; mt < 2; mt++) {
            #pragma unroll
            for (int nt = 0; nt < 8; nt++) {
                const int n  = n0 + wn * 64 + nt * 8 + 2 * lc;
                const int h  = n >> 6;
                const int d  = n & 63;
                const int m1 = m0 + wm * 32 + mt * 16 + lr;
                const int b1 = m1 >> 10, l1 = m1 & 1023;
                *(__half2*)&out[(((size_t)(b1 * HH + h) * LL + l1) * DD) + d] =
                    __floats2half2_rn(acc[mt][nt][0], acc[mt][nt][1]);
                const int m2 = m1 + 8;
                const int b2 = m2 >> 10, l2 = m2 & 1023;
                *(__half2*)&out[(((size_t)(b2 * HH + h) * LL + l2) * DD) + d] =
                    __floats2half2_rn(acc[mt][nt][2], acc[mt][nt][3]);
            }
        }
    } else {
        #pragma unroll
        for (int mt = 0; mt < 2; mt++) {
            #pragma unroll
            for (int nt = 0; nt < 8; nt++) {
                const int n  = n0 + wn * 64 + nt * 8 + 2 * lc;
                const int h  = n >> 6;
                const int d  = n & 63;
                const int m1 = m0 + wm * 32 + mt * 16 + lr;
                const int b1 = m1 >> 10, l1 = m1 & 1023;
                __half* base1 = &g_vt[((size_t)(b1 * HH + h) * DD + d) * LL + l1];
                base1[0]  = __float2half(acc[mt][nt][0]);
                base1[LL] = __float2half(acc[mt][nt][1]);
                const int m2 = m1 + 8;
                const int b2 = m2 >> 10, l2 = m2 & 1023;
                __half* base2 = &g_vt[((size_t)(b2 * HH + h) * DD + d) * LL + l2];
                base2[0]  = __float2half(acc[mt][nt][2]);
                base2[LL] = __float2half(acc[mt][nt][3]);
            }
        }
    }
}

// ===========================================================================
// Flash attention: 128-thread CTAs (4 warps x 16 q-rows, AQT=64) so 4 CTAs
// co-reside per SM and desynchronize softmax/MMA phases. 16 q-tiles paired
// (15-p, p) -> 17 key-tile units per CTA, grid (8,64)=512 CTAs, one wave.
// P stays in registers (S-accum layout == PV A-frag layout).
// Rescale of O skipped (bit-identical) when the running max is unchanged.
// ===========================================================================
#define ATH  128
#define AQT  64
#define AKT  64
#define KVH  (AKT * PRH)
#define QPH  (AQT * PRH)
#define SMEM_ATTN ((4 * KVH + QPH) * (int)sizeof(__half))   // 46080 B

__global__ __launch_bounds__(ATH, 4)
void attn_mma_kernel(float* __restrict__ out)
{
    extern __shared__ __half smh[];
    __half* Ksb[2] = { smh,           smh + KVH };
    __half* Vsb[2] = { smh + 2 * KVH, smh + 3 * KVH };
    __half* QP     = smh + 4 * KVH;     // Q staging

    const int p  = blockIdx.x;          // 0..7
    const int bh = blockIdx.y;
    const int b  = bh >> 3;
    const int h  = bh & 7;

    const __half* Qb  = g_q  + (size_t)bh * LL * DD;
    const __half* Kb  = g_k  + (size_t)bh * LL * DD;
    const __half* Vtb = g_vt + (size_t)bh * DD * LL;

    const int tid  = threadIdx.x;
    const int wid  = tid >> 5;          // 0..3
    const int lane = tid & 31;
    const int lr   = lane >> 2;
    const int lc   = lane & 3;
    const int wq   = wid * 16;

    const int a_row = ((lane >> 3) & 1) * 8 + (lane & 7);
    const int a_kh  = (lane >> 4) * 8;
    const int b_row = (lane >> 4) * 8 + (lane & 7);
    const int b_kh  = ((lane >> 3) & 1) * 8;

    // K/V tiles: 64 rows x 8 chunks = 512 chunks / 128 threads = 4 per thread
    uint32_t kv_dst[4];
    int kv_kc[4], kv_c8[4];
    #pragma unroll
    for (int i = 0; i < 4; i++) {
        const int idx = i * ATH + tid;
        kv_kc[i]  = idx >> 3;
        kv_c8[i]  = idx & 7;
        kv_dst[i] = (uint32_t)((kv_kc[i] * PRH + kv_c8[i] * 8) * 2);
    }
    const uint32_t sk[2] = { smem_u32(Ksb[0]), smem_u32(Ksb[1]) };
    const uint32_t sv[2] = { smem_u32(Vsb[0]), smem_u32(Vsb[1]) };
    const uint32_t sq    = smem_u32(QP);

    const uint32_t aoff = (uint32_t)(((wq + a_row) * PRH) * 2);
    const uint32_t boff = (uint32_t)((b_row * PRH) * 2);

    for (int pass = 0; pass < 2; pass++) {
        const int it = pass ? p : (15 - p);
        const int q0 = it * AQT;

        __syncthreads();
        // Q tile: 64 rows x 8 chunks = 512 chunks / 128 threads = 4 per thread
        #pragma unroll
        for (int i = 0; i < 4; i++) {
            const int idx = i * ATH + tid;
            const int r = idx >> 3;
            const int c8 = idx & 7;
            CP_ASYNC16(sq + (uint32_t)((r * PRH + c8 * 8) * 2),
                       &Qb[(size_t)(q0 + r) * DD + c8 * 8]);
        }
        #pragma unroll
        for (int i = 0; i < 4; i++) {
            CP_ASYNC16(sk[0] + kv_dst[i], &Kb [(size_t)kv_kc[i] * DD + kv_c8[i] * 8]);
            CP_ASYNC16(sv[0] + kv_dst[i], &Vtb[(size_t)kv_kc[i] * LL + kv_c8[i] * 8]);
        }
        CP_COMMIT();
        CP_WAIT0();
        __syncthreads();

        // Build Q fragments via ldmatrix
        uint32_t qf[4][4];
        #pragma unroll
        for (int ks = 0; ks < 4; ks++)
            ldmatrix_x4(qf[ks][0], qf[ks][1], qf[ks][2], qf[ks][3],
                        sq + aoff + (uint32_t)((ks * 16 + a_kh) * 2));

        float oa[8][4];
        #pragma unroll
        for (int nt = 0; nt < 8; nt++)
            #pragma unroll
            for (int q = 0; q < 4; q++) oa[nt][q] = 0.0f;
        float m0v = -1e30f, m1v = -1e30f, l0 = 0.0f, l1 = 0.0f;

        const int jmax = it;
        for (int jt = 0; jt <= jmax; jt++) {
            const int cur = jt & 1;

            if (jt < jmax) {
                const int nxt = cur ^ 1;
                const size_t kbase = (size_t)(jt + 1) * AKT;
                #pragma unroll
                for (int i = 0; i < 4; i++) {
                    CP_ASYNC16(sk[nxt] + kv_dst[i],
                               &Kb[(kbase + kv_kc[i]) * DD + kv_c8[i] * 8]);
                    CP_ASYNC16(sv[nxt] + kv_dst[i],
                               &Vtb[(size_t)kv_kc[i] * LL + kbase + kv_c8[i] * 8]);
                }
                CP_COMMIT();
            }

            // ---- S = Q K^T ----
            float sa2[8][4];
            #pragma unroll
            for (int nt = 0; nt < 8; nt++)
                #pragma unroll
                for (int q = 0; q < 4; q++) sa2[nt][q] = 0.0f;

            #pragma unroll
            for (int ks = 0; ks < 4; ks++) {
                uint32_t bf[8][2];
                #pragma unroll
                for (int ntp = 0; ntp < 4; ntp++) {
                    const uint32_t addr = sk[cur] + boff +
                        (uint32_t)((ntp * 16 * PRH + ks * 16 + b_kh) * 2);
                    ldmatrix_x4(bf[2 * ntp][0], bf[2 * ntp][1],
                                bf[2 * ntp + 1][0], bf[2 * ntp + 1][1], addr);
                }
                #pragma unroll
                for (int nt = 0; nt < 8; nt++)
                    mma_f16_16n8k16(sa2[nt][0], sa2[nt][1], sa2[nt][2], sa2[nt][3],
                                    qf[ks][0], qf[ks][1], qf[ks][2], qf[ks][3],
                                    bf[nt][0], bf[nt][1]);
            }

            // ---- Causal mask (only the diagonal tile jt == it) ----
            const int qg0 = q0 + wq + lr;
            const int qg1 = qg0 + 8;
            if (jt * AKT + AKT - 1 > q0 + wq) {
                #pragma unroll
                for (int nt = 0; nt < 8; nt++) {
                    const int kc0 = jt * AKT + nt * 8 + 2 * lc;
                    if (kc0     > qg0) sa2[nt][0] = -1e30f;
                    if (kc0 + 1 > qg0) sa2[nt][1] = -1e30f;
                    if (kc0     > qg1) sa2[nt][2] = -1e30f;
                    if (kc0 + 1 > qg1) sa2[nt][3] = -1e30f;
                }
            }

            // ---- Online softmax (log2 domain); P packed straight to frags ----
            float tmax0 = -1e30f, tmax1 = -1e30f;
            #pragma unroll
            for (int nt = 0; nt < 8; nt++) {
                tmax0 = fmaxf(tmax0, fmaxf(sa2[nt][0], sa2[nt][1]));
                tmax1 = fmaxf(tmax1, fmaxf(sa2[nt][2], sa2[nt][3]));
            }
            tmax0 = fmaxf(tmax0, __shfl_xor_sync(0xffffffffu, tmax0, 1));
            tmax0 = fmaxf(tmax0, __shfl_xor_sync(0xffffffffu, tmax0, 2));
            tmax1 = fmaxf(tmax1, __shfl_xor_sync(0xffffffffu, tmax1, 1));
            tmax1 = fmaxf(tmax1, __shfl_xor_sync(0xffffffffu, tmax1, 2));

            const float mn0 = fmaxf(m0v, tmax0);
            const float mn1 = fmaxf(m1v, tmax1);
            const float f0  = ex2f(m0v - mn0);
            const float f1  = ex2f(m1v - mn1);
            const bool need = (mn0 != m0v) | (mn1 != m1v);

            uint32_t pf[4][4];
            float rs0 = 0.0f, rs1 = 0.0f;
            #pragma unroll
            for (int nt = 0; nt < 8; nt++) {
                const float p00 = ex2f(sa2[nt][0] - mn0);
                const float p01 = ex2f(sa2[nt][1] - mn0);
                const float p10 = ex2f(sa2[nt][2] - mn1);
                const float p11 = ex2f(sa2[nt][3] - mn1);
                rs0 += p00 + p01;
                rs1 += p10 + p11;
                const int kk  = nt >> 1;
                const int sub = (nt & 1) * 2;
                pf[kk][sub + 0] = h2u(__floats2half2_rn(p00, p01));
                pf[kk][sub + 1] = h2u(__floats2half2_rn(p10, p11));
            }
            rs0 += __shfl_xor_sync(0xffffffffu, rs0, 1);
            rs0 += __shfl_xor_sync(0xffffffffu, rs0, 2);
            rs1 += __shfl_xor_sync(0xffffffffu, rs1, 1);
            rs1 += __shfl_xor_sync(0xffffffffu, rs1, 2);

            l0 = l0 * f0 + rs0;  m0v = mn0;
            l1 = l1 * f1 + rs1;  m1v = mn1;
            // Skip O rescale when no lane's max moved (f==1.0 exactly).
            if (__any_sync(0xffffffffu, need)) {
                #pragma unroll
                for (int nt = 0; nt < 8; nt++) {
                    oa[nt][0] *= f0;  oa[nt][1] *= f0;
                    oa[nt][2] *= f1;  oa[nt][3] *= f1;
                }
            }

            // ---- O += P V  (pf registers; vf via ldmatrix) ----
            #pragma unroll
            for (int ks = 0; ks < 4; ks++) {
                uint32_t vf[8][2];
                #pragma unroll
                for (int ntp = 0; ntp < 4; ntp++) {
                    const uint32_t addr = sv[cur] + boff +
                        (uint32_t)((ntp * 16 * PRH + ks * 16 + b_kh) * 2);
                    ldmatrix_x4(vf[2 * ntp][0], vf[2 * ntp][1],
                                vf[2 * ntp + 1][0], vf[2 * ntp + 1][1], addr);
                }
                #pragma unroll
                for (int nt = 0; nt < 8; nt++)
                    mma_f16_16n8k16(oa[nt][0], oa[nt][1], oa[nt][2], oa[nt][3],
                                    pf[ks][0], pf[ks][1], pf[ks][2], pf[ks][3],
                                    vf[nt][0], vf[nt][1]);
            }

            if (jt < jmax) CP_WAIT0();
            __syncthreads();
        }

        // ---- Epilogue (fp32 out) ----
        const float inv0 = 1.0f / l0;
        const float inv1 = 1.0f / l1;
        const int q1 = q0 + wq + lr;
        const int q2 = q1 + 8;
        #pragma unroll
        for (int nt = 0; nt < 8; nt++) {
            const int d = nt * 8 + 2 * lc;
            *(float2*)&out[((size_t)(b * LL + q1)) * DOUT + h * DD + d] =
                make_float2(oa[nt][0] * inv0, oa[nt][1] * inv0);
            *(float2*)&out[((size_t)(b * LL + q2)) * DOUT + h * DD + d] =
                make_float2(oa[nt][2] * inv1, oa[nt][3] * inv1);
        }
    }
}

// ---------------------------------------------------------------------------
extern "C" void kernel_launch(void* const* d_in, const int* in_sizes, int n_in,
                              void* d_out, int out_size)
{
    const float* Qseq = (const float*)d_in[0];
    const float* Kseq = (const float*)d_in[1];
    const float* Vseq = (const float*)d_in[2];
    const float* WQ   = (const float*)d_in[3];
    const float* WK   = (const float*)d_in[4];
    const float* WV   = (const float*)d_in[5];
    float* out = (float*)d_out;

    cudaFuncSetAttribute(proj_mma_kernel,
                         cudaFuncAttributeMaxDynamicSharedMemorySize, SMEM_PROJ);
    cudaFuncSetAttribute(attn_mma_kernel,
                         cudaFuncAttributeMaxDynamicSharedMemorySize, SMEM_ATTN);

    dim3 ppgrd(1024 + 256, 1, 3);
    prepass_kernel<<<ppgrd, 256>>>(Qseq, Kseq, Vseq, WQ, WK, WV);

    dim3 pgrd(DOUT / PTN, MM / PTM, 3);      // (4, 64, 3)
    proj_mma_kernel<<<pgrd, 256, SMEM_PROJ>>>();

    dim3 agrd(8, BB * HH);                   // 512 CTAs, 4/SM, one wave
    attn_mma_kernel<<<agrd, ATH, SMEM_ATTN>>>(out);
}

// round 13
// speedup vs baseline: 1.4565x; 1.4565x over previous
#include <cuda_runtime.h>
#include <cuda_fp16.h>
#include <cstdint>

// Problem constants
#define BB   8
#define LL   1024
#define DIN  512
#define HH   8
#define DD   64
#define DOUT 512
#define MM   (BB * LL)   // 8192

// Half-precision staging buffers
__device__ __half g_xh[3 * MM * DIN];       // inputs converted to half
__device__ __half g_wth[3 * DIN * DOUT];    // Wt[n][k] half; WQ pre-scaled by 0.125*log2e
__device__ __half g_q [BB * HH * LL * DD];  // [b,h,l,d], pre-scaled
__device__ __half g_k [BB * HH * LL * DD];  // [b,h,l,d]
__device__ __half g_vt[BB * HH * DD * LL];  // [b,h,d,l]  (V transposed)

// ===========================================================================
// Helpers
// ===========================================================================
__device__ __forceinline__ float ex2f(float x) {
    float y;
    asm("ex2.approx.ftz.f32 %0, %1;" : "=f"(y) : "f"(x));
    return y;
}

__device__ __forceinline__ void mma_f16_16n8k16(float& d0, float& d1, float& d2, float& d3,
                                                uint32_t a0, uint32_t a1, uint32_t a2, uint32_t a3,
                                                uint32_t b0, uint32_t b1) {
    asm volatile(
        "mma.sync.aligned.m16n8k16.row.col.f32.f16.f16.f32 "
        "{%0,%1,%2,%3}, {%4,%5,%6,%7}, {%8,%9}, {%0,%1,%2,%3};"
        : "+f"(d0), "+f"(d1), "+f"(d2), "+f"(d3)
        : "r"(a0), "r"(a1), "r"(a2), "r"(a3), "r"(b0), "r"(b1));
}

__device__ __forceinline__ void ldmatrix_x4(uint32_t& r0, uint32_t& r1,
                                            uint32_t& r2, uint32_t& r3, uint32_t addr) {
    asm volatile("ldmatrix.sync.aligned.m8n8.x4.shared.b16 {%0,%1,%2,%3}, [%4];"
                 : "=r"(r0), "=r"(r1), "=r"(r2), "=r"(r3) : "r"(addr));
}

__device__ __forceinline__ uint32_t smem_u32(const void* p) {
    uint32_t a;
    asm("{ .reg .u64 t; cvta.to.shared.u64 t, %1; cvt.u32.u64 %0, t; }"
        : "=r"(a) : "l"(p));
    return a;
}

__device__ __forceinline__ uint32_t h2u(__half2 h) {
    uint32_t u;
    asm("mov.b32 %0, %1;" : "=r"(u) : "r"(*(uint32_t*)&h));
    return u;
}

#define CP_ASYNC16(dst_u32, src_ptr) \
    asm volatile("cp.async.cg.shared.global [%0], [%1], 16;" :: "r"(dst_u32), "l"(src_ptr))
#define CP_COMMIT()  asm volatile("cp.async.commit_group;" ::: "memory")
#define CP_WAIT0()   asm volatile("cp.async.wait_group 0;" ::: "memory")

// ===========================================================================
// Fused pre-pass: convert X->half AND transpose/convert W (round-11 config).
// ===========================================================================
__global__ void prepass_kernel(const float* __restrict__ Q, const float* __restrict__ K,
                               const float* __restrict__ V,
                               const float* __restrict__ Wq, const float* __restrict__ Wk,
                               const float* __restrict__ Wv)
{
    const int z  = blockIdx.z;
    const int bx = blockIdx.x;
    const int tid = threadIdx.x;

    if (bx < 4096) {
        const float* src = (z == 0) ? Q : (z == 1) ? K : V;
        __half2* dst = (__half2*)(g_xh + (size_t)z * MM * DIN);
        const int i = bx * 256 + tid;
        const float4 v = ((const float4*)src)[i];
        dst[2 * i + 0] = __floats2half2_rn(v.x, v.y);
        dst[2 * i + 1] = __floats2half2_rn(v.z, v.w);
    } else {
        const float* W = (z == 0) ? Wq : (z == 1) ? Wk : Wv;
        __half* Wt = g_wth + (size_t)z * DIN * DOUT;
        const float s = (z == 0) ? 0.125f * 1.4426950408889634f : 1.0f;

        __shared__ float t[32][33];
        const int tile = bx - 4096;
        const int bxt  = tile & 15;
        const int byt  = tile >> 4;
        const int tx = tid & 31, ty = tid >> 5;
        int x = bxt * 32 + tx;
        int y = byt * 32 + ty;
        #pragma unroll
        for (int j = 0; j < 32; j += 8)
            t[ty + j][tx] = W[(size_t)(y + j) * DOUT + x];
        __syncthreads();
        x = byt * 32 + tx;
        y = bxt * 32 + ty;
        #pragma unroll
        for (int j = 0; j < 32; j += 8)
            Wt[(size_t)(y + j) * DIN + x] = __float2half(t[tx][ty + j] * s);
    }
}

// ===========================================================================
// fp16 mma.sync projection with ldmatrix fragment loads. (validated round 10)
// ===========================================================================
#define PTM 128
#define PTN 128
#define PTK 64
#define PKT (DIN / PTK)    // 8
#define PRH 72             // halves per smem row
#define PRW 36             // words per smem row
#define TILE_H (PTM * PRH)
#define SMEM_PROJ (4 * TILE_H * (int)sizeof(__half))   // 73728 B

__global__ __launch_bounds__(256)
void proj_mma_kernel()
{
    extern __shared__ __half smh[];
    __half* As[2] = { smh,              smh + TILE_H };
    __half* Bs[2] = { smh + 2 * TILE_H, smh + 3 * TILE_H };

    const int z = blockIdx.z;
    const __half* X  = g_xh  + (size_t)z * MM * DIN;
    const __half* Wt = g_wth + (size_t)z * DIN * DOUT;

    const int tid  = threadIdx.x;
    const int wid  = tid >> 5;
    const int lane = tid & 31;
    const int wm   = wid & 3;
    const int wn   = wid >> 2;
    const int m0   = blockIdx.y * PTM;
    const int n0   = blockIdx.x * PTN;
    const int lr   = lane >> 2;
    const int lc   = lane & 3;

    const int a_row = ((lane >> 3) & 1) * 8 + (lane & 7);
    const int a_kh  = (lane >> 4) * 8;
    const int b_row = (lane >> 4) * 8 + (lane & 7);
    const int b_kh  = ((lane >> 3) & 1) * 8;

    uint32_t dsto[4];
    const __half* a_src[4];
    const __half* b_src[4];
    #pragma unroll
    for (int i = 0; i < 4; i++) {
        const int idx = i * 256 + tid;
        const int r   = idx >> 3;
        const int c8  = idx & 7;
        dsto[i] = (uint32_t)((r * PRH + c8 * 8) * 2);
        a_src[i] = &X [(size_t)(m0 + r) * DIN + c8 * 8];
        b_src[i] = &Wt[(size_t)(n0 + r) * DIN + c8 * 8];
    }
    const uint32_t sa[2] = { smem_u32(As[0]), smem_u32(As[1]) };
    const uint32_t sb[2] = { smem_u32(Bs[0]), smem_u32(Bs[1]) };

    float acc[2][8][4];
    #pragma unroll
    for (int mt = 0; mt < 2; mt++)
        #pragma unroll
        for (int nt = 0; nt < 8; nt++)
            #pragma unroll
            for (int q = 0; q < 4; q++) acc[mt][nt][q] = 0.0f;

    #pragma unroll
    for (int i = 0; i < 4; i++) {
        CP_ASYNC16(sa[0] + dsto[i], a_src[i]);
        CP_ASYNC16(sb[0] + dsto[i], b_src[i]);
    }
    CP_COMMIT();
    CP_WAIT0();
    __syncthreads();

    for (int kt = 0; kt < PKT; kt++) {
        const int cur = kt & 1;
        if (kt + 1 < PKT) {
            const int nxt = cur ^ 1;
            const int koff = (kt + 1) * PTK;
            #pragma unroll
            for (int i = 0; i < 4; i++) {
                CP_ASYNC16(sa[nxt] + dsto[i], a_src[i] + koff);
                CP_ASYNC16(sb[nxt] + dsto[i], b_src[i] + koff);
            }
            CP_COMMIT();
        }

        const uint32_t Abase = sa[cur];
        const uint32_t Bbase = sb[cur];
        #pragma unroll
        for (int ks = 0; ks < 4; ks++) {
            uint32_t af[2][4];
            #pragma unroll
            for (int mt = 0; mt < 2; mt++) {
                const uint32_t addr = Abase +
                    (uint32_t)(((wm * 32 + mt * 16 + a_row) * PRH + ks * 16 + a_kh) * 2);
                ldmatrix_x4(af[mt][0], af[mt][1], af[mt][2], af[mt][3], addr);
            }
            uint32_t bf[8][2];
            #pragma unroll
            for (int ntp = 0; ntp < 4; ntp++) {
                const uint32_t addr = Bbase +
                    (uint32_t)(((wn * 64 + ntp * 16 + b_row) * PRH + ks * 16 + b_kh) * 2);
                ldmatrix_x4(bf[2 * ntp][0], bf[2 * ntp][1],
                            bf[2 * ntp + 1][0], bf[2 * ntp + 1][1], addr);
            }
            #pragma unroll
            for (int mt = 0; mt < 2; mt++)
                #pragma unroll
                for (int nt = 0; nt < 8; nt++)
                    mma_f16_16n8k16(acc[mt][nt][0], acc[mt][nt][1],
                                    acc[mt][nt][2], acc[mt][nt][3],
                                    af[mt][0], af[mt][1], af[mt][2], af[mt][3],
                                    bf[nt][0], bf[nt][1]);
        }

        if (kt + 1 < PKT) CP_WAIT0();
        __syncthreads();
    }

    if (z < 2) {
        __half* out = (z == 0) ? g_q : g_k;
        #pragma unroll
        for (int mt = 0; mt < 2; mt++) {
            #pragma unroll
            for (int nt = 0; nt < 8; nt++) {
                const int n  = n0 + wn * 64 + nt * 8 + 2 * lc;
                const int h  = n >> 6;
                const int d  = n & 63;
                const int m1 = m0 + wm * 32 + mt * 16 + lr;
                const int b1 = m1 >> 10, l1 = m1 & 1023;
                *(__half2*)&out[(((size_t)(b1 * HH + h) * LL + l1) * DD) + d] =
                    __floats2half2_rn(acc[mt][nt][0], acc[mt][nt][1]);
                const int m2 = m1 + 8;
                const int b2 = m2 >> 10, l2 = m2 & 1023;
                *(__half2*)&out[(((size_t)(b2 * HH + h) * LL + l2) * DD) + d] =
                    __floats2half2_rn(acc[mt][nt][2], acc[mt][nt][3]);
            }
        }
    } else {
        #pragma unroll
        for (int mt = 0; mt < 2; mt++) {
            #pragma unroll
            for (int nt = 0; nt < 8; nt++) {
                const int n  = n0 + wn * 64 + nt * 8 + 2 * lc;
                const int h  = n >> 6;
                const int d  = n & 63;
                const int m1 = m0 + wm * 32 + mt * 16 + lr;
                const int b1 = m1 >> 10, l1 = m1 & 1023;
                __half* base1 = &g_vt[((size_t)(b1 * HH + h) * DD + d) * LL + l1];
                base1[0]  = __float2half(acc[mt][nt][0]);
                base1[LL] = __float2half(acc[mt][nt][1]);
                const int m2 = m1 + 8;
                const int b2 = m2 >> 10, l2 = m2 & 1023;
                __half* base2 = &g_vt[((size_t)(b2 * HH + h) * DD + d) * LL + l2];
                base2[0]  = __float2half(acc[mt][nt][2]);
                base2[LL] = __float2half(acc[mt][nt][3]);
            }
        }
    }
}

// ===========================================================================
// Flash attention (round-11 config: 256 thr, AQT=128, 2 CTAs/SM, pairing
// (7-p, p)) + O-rescale skip when the running max is unchanged (bit-identical).
// P stays in registers (S-accum layout == PV A-frag layout).
// ===========================================================================
#define AQT  128
#define AKT  64
#define KVH  (AKT * PRH)
#define QPH  (AQT * PRH)
#define SMEM_ATTN ((4 * KVH + QPH) * (int)sizeof(__half))   // 55296 B

__global__ __launch_bounds__(256, 2)
void attn_mma_kernel(float* __restrict__ out)
{
    extern __shared__ __half smh[];
    __half* Ksb[2] = { smh,           smh + KVH };
    __half* Vsb[2] = { smh + 2 * KVH, smh + 3 * KVH };
    __half* QP     = smh + 4 * KVH;     // Q staging only

    const int p  = blockIdx.x;          // 0..3
    const int bh = blockIdx.y;
    const int b  = bh >> 3;
    const int h  = bh & 7;

    const __half* Qb  = g_q  + (size_t)bh * LL * DD;
    const __half* Kb  = g_k  + (size_t)bh * LL * DD;
    const __half* Vtb = g_vt + (size_t)bh * DD * LL;

    const int tid  = threadIdx.x;
    const int wid  = tid >> 5;
    const int lane = tid & 31;
    const int lr   = lane >> 2;
    const int lc   = lane & 3;
    const int wq   = wid * 16;

    const int a_row = ((lane >> 3) & 1) * 8 + (lane & 7);
    const int a_kh  = (lane >> 4) * 8;
    const int b_row = (lane >> 4) * 8 + (lane & 7);
    const int b_kh  = ((lane >> 3) & 1) * 8;

    uint32_t kv_dst[2];
    int kv_kc[2], kv_c8[2];
    #pragma unroll
    for (int i = 0; i < 2; i++) {
        const int idx = i * 256 + tid;
        kv_kc[i]  = idx >> 3;
        kv_c8[i]  = idx & 7;
        kv_dst[i] = (uint32_t)((kv_kc[i] * PRH + kv_c8[i] * 8) * 2);
    }
    const uint32_t sk[2] = { smem_u32(Ksb[0]), smem_u32(Ksb[1]) };
    const uint32_t sv[2] = { smem_u32(Vsb[0]), smem_u32(Vsb[1]) };
    const uint32_t sq    = smem_u32(QP);

    const uint32_t aoff = (uint32_t)(((wq + a_row) * PRH) * 2);
    const uint32_t boff = (uint32_t)((b_row * PRH) * 2);

    for (int pass = 0; pass < 2; pass++) {
        const int it = pass ? p : (7 - p);
        const int q0 = it * AQT;

        __syncthreads();
        #pragma unroll
        for (int i = 0; i < 4; i++) {
            const int idx = i * 256 + tid;
            const int r = idx >> 3;
            const int c8 = idx & 7;
            CP_ASYNC16(sq + (uint32_t)((r * PRH + c8 * 8) * 2),
                       &Qb[(size_t)(q0 + r) * DD + c8 * 8]);
        }
        #pragma unroll
        for (int i = 0; i < 2; i++) {
            CP_ASYNC16(sk[0] + kv_dst[i], &Kb [(size_t)kv_kc[i] * DD + kv_c8[i] * 8]);
            CP_ASYNC16(sv[0] + kv_dst[i], &Vtb[(size_t)kv_kc[i] * LL + kv_c8[i] * 8]);
        }
        CP_COMMIT();
        CP_WAIT0();
        __syncthreads();

        // Build Q fragments via ldmatrix
        uint32_t qf[4][4];
        #pragma unroll
        for (int ks = 0; ks < 4; ks++)
            ldmatrix_x4(qf[ks][0], qf[ks][1], qf[ks][2], qf[ks][3],
                        sq + aoff + (uint32_t)((ks * 16 + a_kh) * 2));

        float oa[8][4];
        #pragma unroll
        for (int nt = 0; nt < 8; nt++)
            #pragma unroll
            for (int q = 0; q < 4; q++) oa[nt][q] = 0.0f;
        float m0v = -1e30f, m1v = -1e30f, l0 = 0.0f, l1 = 0.0f;

        const int jmax = 2 * it + 1;
        for (int jt = 0; jt <= jmax; jt++) {
            const int cur = jt & 1;

            if (jt < jmax) {
                const int nxt = cur ^ 1;
                const size_t kbase = (size_t)(jt + 1) * AKT;
                #pragma unroll
                for (int i = 0; i < 2; i++) {
                    CP_ASYNC16(sk[nxt] + kv_dst[i],
                               &Kb[(kbase + kv_kc[i]) * DD + kv_c8[i] * 8]);
                    CP_ASYNC16(sv[nxt] + kv_dst[i],
                               &Vtb[(size_t)kv_kc[i] * LL + kbase + kv_c8[i] * 8]);
                }
                CP_COMMIT();
            }

            // ---- S = Q K^T ----
            float sa2[8][4];
            #pragma unroll
            for (int nt = 0; nt < 8; nt++)
                #pragma unroll
                for (int q = 0; q < 4; q++) sa2[nt][q] = 0.0f;

            #pragma unroll
            for (int ks = 0; ks < 4; ks++) {
                uint32_t bf[8][2];
                #pragma unroll
                for (int ntp = 0; ntp < 4; ntp++) {
                    const uint32_t addr = sk[cur] + boff +
                        (uint32_t)((ntp * 16 * PRH + ks * 16 + b_kh) * 2);
                    ldmatrix_x4(bf[2 * ntp][0], bf[2 * ntp][1],
                                bf[2 * ntp + 1][0], bf[2 * ntp + 1][1], addr);
                }
                #pragma unroll
                for (int nt = 0; nt < 8; nt++)
                    mma_f16_16n8k16(sa2[nt][0], sa2[nt][1], sa2[nt][2], sa2[nt][3],
                                    qf[ks][0], qf[ks][1], qf[ks][2], qf[ks][3],
                                    bf[nt][0], bf[nt][1]);
            }

            // ---- Causal mask ----
            const int qg0 = q0 + wq + lr;
            const int qg1 = qg0 + 8;
            if (jt * AKT + AKT - 1 > q0 + wq) {
                #pragma unroll
                for (int nt = 0; nt < 8; nt++) {
                    const int kc0 = jt * AKT + nt * 8 + 2 * lc;
                    if (kc0     > qg0) sa2[nt][0] = -1e30f;
                    if (kc0 + 1 > qg0) sa2[nt][1] = -1e30f;
                    if (kc0     > qg1) sa2[nt][2] = -1e30f;
                    if (kc0 + 1 > qg1) sa2[nt][3] = -1e30f;
                }
            }

            // ---- Online softmax (log2 domain); P packed straight to frags ----
            float tmax0 = -1e30f, tmax1 = -1e30f;
            #pragma unroll
            for (int nt = 0; nt < 8; nt++) {
                tmax0 = fmaxf(tmax0, fmaxf(sa2[nt][0], sa2[nt][1]));
                tmax1 = fmaxf(tmax1, fmaxf(sa2[nt][2], sa2[nt][3]));
            }
            tmax0 = fmaxf(tmax0, __shfl_xor_sync(0xffffffffu, tmax0, 1));
            tmax0 = fmaxf(tmax0, __shfl_xor_sync(0xffffffffu, tmax0, 2));
            tmax1 = fmaxf(tmax1, __shfl_xor_sync(0xffffffffu, tmax1, 1));
            tmax1 = fmaxf(tmax1, __shfl_xor_sync(0xffffffffu, tmax1, 2));

            const float mn0 = fmaxf(m0v, tmax0);
            const float mn1 = fmaxf(m1v, tmax1);
            const float f0  = ex2f(m0v - mn0);
            const float f1  = ex2f(m1v - mn1);
            const bool need = (mn0 != m0v) | (mn1 != m1v);

            uint32_t pf[4][4];
            float rs0 = 0.0f, rs1 = 0.0f;
            #pragma unroll
            for (int nt = 0; nt < 8; nt++) {
                const float p00 = ex2f(sa2[nt][0] - mn0);
                const float p01 = ex2f(sa2[nt][1] - mn0);
                const float p10 = ex2f(sa2[nt][2] - mn1);
                const float p11 = ex2f(sa2[nt][3] - mn1);
                rs0 += p00 + p01;
                rs1 += p10 + p11;
                const int kk  = nt >> 1;
                const int sub = (nt & 1) * 2;
                pf[kk][sub + 0] = h2u(__floats2half2_rn(p00, p01));
                pf[kk][sub + 1] = h2u(__floats2half2_rn(p10, p11));
            }
            rs0 += __shfl_xor_sync(0xffffffffu, rs0, 1);
            rs0 += __shfl_xor_sync(0xffffffffu, rs0, 2);
            rs1 += __shfl_xor_sync(0xffffffffu, rs1, 1);
            rs1 += __shfl_xor_sync(0xffffffffu, rs1, 2);

            l0 = l0 * f0 + rs0;  m0v = mn0;
            l1 = l1 * f1 + rs1;  m1v = mn1;
            // Skip O rescale when no lane's max moved (f==1.0 exactly).
            if (__any_sync(0xffffffffu, need)) {
                #pragma unroll
                for (int nt = 0; nt < 8; nt++) {
                    oa[nt][0] *= f0;  oa[nt][1] *= f0;
                    oa[nt][2] *= f1;  oa[nt][3] *= f1;
                }
            }

            // ---- O += P V  (pf from registers; vf via ldmatrix) ----
            #pragma unroll
            for (int ks = 0; ks < 4; ks++) {
                uint32_t vf[8][2];
                #pragma unroll
                for (int ntp = 0; ntp < 4; ntp++) {
                    const uint32_t addr = sv[cur] + boff +
                        (uint32_t)((ntp * 16 * PRH + ks * 16 + b_kh) * 2);
                    ldmatrix_x4(vf[2 * ntp][0], vf[2 * ntp][1],
                                vf[2 * ntp + 1][0], vf[2 * ntp + 1][1], addr);
                }
                #pragma unroll
                for (int nt = 0; nt < 8; nt++)
                    mma_f16_16n8k16(oa[nt][0], oa[nt][1], oa[nt][2], oa[nt][3],
                                    pf[ks][0], pf[ks][1], pf[ks][2], pf[ks][3],
                                    vf[nt][0], vf[nt][1]);
            }

            if (jt < jmax) CP_WAIT0();
            __syncthreads();
        }

        // ---- Epilogue (fp32 out) ----
        const float inv0 = 1.0f / l0;
        const float inv1 = 1.0f / l1;
        const int q1 = q0 + wq + lr;
        const int q2 = q1 + 8;
        #pragma unroll
        for (int nt = 0; nt < 8; nt++) {
            const int d = nt * 8 + 2 * lc;
            *(float2*)&out[((size_t)(b * LL + q1)) * DOUT + h * DD + d] =
                make_float2(oa[nt][0] * inv0, oa[nt][1] * inv0);
            *(float2*)&out[((size_t)(b * LL + q2)) * DOUT + h * DD + d] =
                make_float2(oa[nt][2] * inv1, oa[nt][3] * inv1);
        }
    }
}

// ---------------------------------------------------------------------------
extern "C" void kernel_launch(void* const* d_in, const int* in_sizes, int n_in,
                              void* d_out, int out_size)
{
    const float* Qseq = (const float*)d_in[0];
    const float* Kseq = (const float*)d_in[1];
    const float* Vseq = (const float*)d_in[2];
    const float* WQ   = (const float*)d_in[3];
    const float* WK   = (const float*)d_in[4];
    const float* WV   = (const float*)d_in[5];
    float* out = (float*)d_out;

    cudaFuncSetAttribute(proj_mma_kernel,
                         cudaFuncAttributeMaxDynamicSharedMemorySize, SMEM_PROJ);
    cudaFuncSetAttribute(attn_mma_kernel,
                         cudaFuncAttributeMaxDynamicSharedMemorySize, SMEM_ATTN);

    dim3 ppgrd(4096 + 256, 1, 3);
    prepass_kernel<<<ppgrd, 256>>>(Qseq, Kseq, Vseq, WQ, WK, WV);

    dim3 pgrd(DOUT / PTN, MM / PTM, 3);      // (4, 64, 3)
    proj_mma_kernel<<<pgrd, 256, SMEM_PROJ>>>();

    dim3 agrd(4, BB * HH);                   // 256 CTAs, one balanced wave
    attn_mma_kernel<<<agrd, 256, SMEM_ATTN>>>(out);
}